// round 10
// baseline (speedup 1.0000x reference)
#include <cuda_runtime.h>
#include <stdint.h>

#define D 128
#define MAX_NODES 100000
#define NSM 148
#define GBM 128                 // GEMM tile rows
#define AST 129                 // A smem stride (odd -> conflict-free)
#define ASZ (D * AST)           // floats per A buffer

// 51.2 MB scratch for y = x_out @ W0
__device__ float g_y[MAX_NODES * D];
__device__ int   g_bad;         // nonzero -> edge_index is int32

// ---------------------------------------------------------------------------
// helpers
// ---------------------------------------------------------------------------
__device__ __forceinline__ void ldg_el32B(const float* p, float4& lo, float4& hi) {
    unsigned long long x0, x1, x2, x3;
    asm volatile("ld.global.nc.L2::evict_last.v4.b64 {%0,%1,%2,%3}, [%4];"
                 : "=l"(x0), "=l"(x1), "=l"(x2), "=l"(x3) : "l"(p));
    lo.x = __uint_as_float((unsigned)x0); lo.y = __uint_as_float((unsigned)(x0 >> 32));
    lo.z = __uint_as_float((unsigned)x1); lo.w = __uint_as_float((unsigned)(x1 >> 32));
    hi.x = __uint_as_float((unsigned)x2); hi.y = __uint_as_float((unsigned)(x2 >> 32));
    hi.z = __uint_as_float((unsigned)x3); hi.w = __uint_as_float((unsigned)(x3 >> 32));
}
__device__ __forceinline__ void stg_el32B(float* p, unsigned long long x0,
                                          unsigned long long x1,
                                          unsigned long long x2,
                                          unsigned long long x3) {
    asm volatile("st.global.L2::evict_last.v4.b64 [%0], {%1,%2,%3,%4};"
                 :: "l"(p), "l"(x0), "l"(x1), "l"(x2), "l"(x3) : "memory");
}
__device__ __forceinline__ void cp_async4(uint32_t smem_addr, const float* gptr) {
    asm volatile("cp.async.ca.shared.global [%0], [%1], 4;"
                 :: "r"(smem_addr), "l"(gptr));
}

// ---------------------------------------------------------------------------
// Persistent GEMM: y = x_out @ W0.  148 CTAs x 1024 threads (32 warps/SM).
// W resident in smem; A tiles (128x128) double-buffered via cp.async.
// Thread computes 2 rows x 8 cols as 8 packed f32x2 accumulators.
// Per warp-kk: 2 A-LDS + 2 W-broadcast wavefronts vs 8 FFMA2 — balanced.
// ---------------------------------------------------------------------------
__global__ void __launch_bounds__(1024, 1) gemm_xout_w(
    const float* __restrict__ x_out,
    const float* __restrict__ W,   // [D*D] row-major W[k*D + c]
    int n)
{
    extern __shared__ float smem[];
    float* Ws = smem;              // [k*128 + c], 64 KB
    float* As = smem + D * D;      // 2 buffers of [k*129 + r]

    const int tid    = threadIdx.x;
    const int bid    = blockIdx.x;
    const int ntiles = (n + GBM - 1) / GBM;

    // load W once (coalesced float4)
    #pragma unroll
    for (int i = tid; i < (D * D) / 4; i += 1024)
        ((float4*)Ws)[i] = ((const float4*)W)[i];

    uint32_t as_base;
    asm("{ .reg .u64 t; cvta.to.shared.u64 t, %1; cvt.u32.u64 %0, t; }"
        : "=r"(as_base) : "l"(As));

    const int kS = tid & 127;      // staging: fixed k
    const int rS = tid >> 7;       // staging: row sub-index 0..7

    // prologue: stage tile bid into buffer 0
    if (bid < ntiles) {
        #pragma unroll
        for (int p = 0; p < 16; p++) {
            int rr = p * 8 + rS;
            int grow = bid * GBM + rr;
            if (grow >= n) grow = n - 1;
            cp_async4(as_base + (uint32_t)(kS * AST + rr) * 4,
                      &x_out[(size_t)grow * D + kS]);
        }
        asm volatile("cp.async.commit_group;");
    }

    const int r0 = tid & 63;       // rows r0, r0+64
    const int cg = tid >> 6;       // 0..15 -> cols cg*8..+7

    int buf = 0;
    for (int t = bid; t < ntiles; t += NSM) {
        bool has_next = (t + NSM) < ntiles;
        if (has_next) {
            int tn = t + NSM;
            uint32_t dstb = as_base + (uint32_t)((buf ^ 1) * ASZ) * 4;
            #pragma unroll
            for (int p = 0; p < 16; p++) {
                int rr = p * 8 + rS;
                int grow = tn * GBM + rr;
                if (grow >= n) grow = n - 1;
                cp_async4(dstb + (uint32_t)(kS * AST + rr) * 4,
                          &x_out[(size_t)grow * D + kS]);
            }
            asm volatile("cp.async.commit_group;");
            asm volatile("cp.async.wait_group 1;");
        } else {
            asm volatile("cp.async.wait_group 0;");
        }
        __syncthreads();           // current buffer visible to all

        const float* A = As + buf * ASZ;
        unsigned long long acc[8];
        #pragma unroll
        for (int j = 0; j < 8; j++) acc[j] = 0ull;

        #pragma unroll 4
        for (int kk = 0; kk < D; kk++) {
            float a0 = A[kk * AST + r0];
            float a1 = A[kk * AST + r0 + 64];
            unsigned long long aa0, aa1;
            asm("mov.b64 %0, {%1, %1};" : "=l"(aa0) : "r"(__float_as_uint(a0)));
            asm("mov.b64 %0, {%1, %1};" : "=l"(aa1) : "r"(__float_as_uint(a1)));
            const ulonglong2* wp = reinterpret_cast<const ulonglong2*>(&Ws[kk * D + cg * 8]);
            ulonglong2 u0 = wp[0];   // cols +0..3
            ulonglong2 u1 = wp[1];   // cols +4..7
            asm("fma.rn.f32x2 %0, %1, %2, %0;" : "+l"(acc[0]) : "l"(aa0), "l"(u0.x));
            asm("fma.rn.f32x2 %0, %1, %2, %0;" : "+l"(acc[1]) : "l"(aa0), "l"(u0.y));
            asm("fma.rn.f32x2 %0, %1, %2, %0;" : "+l"(acc[2]) : "l"(aa0), "l"(u1.x));
            asm("fma.rn.f32x2 %0, %1, %2, %0;" : "+l"(acc[3]) : "l"(aa0), "l"(u1.y));
            asm("fma.rn.f32x2 %0, %1, %2, %0;" : "+l"(acc[4]) : "l"(aa1), "l"(u0.x));
            asm("fma.rn.f32x2 %0, %1, %2, %0;" : "+l"(acc[5]) : "l"(aa1), "l"(u0.y));
            asm("fma.rn.f32x2 %0, %1, %2, %0;" : "+l"(acc[6]) : "l"(aa1), "l"(u1.x));
            asm("fma.rn.f32x2 %0, %1, %2, %0;" : "+l"(acc[7]) : "l"(aa1), "l"(u1.y));
        }

        int gr0 = t * GBM + r0;
        int gr1 = gr0 + 64;
        if (gr0 < n)
            stg_el32B(g_y + (size_t)gr0 * D + cg * 8, acc[0], acc[1], acc[2], acc[3]);
        if (gr1 < n)
            stg_el32B(g_y + (size_t)gr1 * D + cg * 8, acc[4], acc[5], acc[6], acc[7]);

        __syncthreads();           // compute done before buffer is restaged
        buf ^= 1;
    }
}

// ---------------------------------------------------------------------------
// dtype detection
// ---------------------------------------------------------------------------
__global__ void detect_dtype(const unsigned int* __restrict__ ei_raw, int nwords)
{
    __shared__ int bad;
    if (threadIdx.x == 0) bad = 0;
    __syncthreads();
    int limit = 1024;
    if (limit > nwords) limit = nwords & ~1;
    for (int i = threadIdx.x; i * 2 + 1 < limit; i += blockDim.x)
        if (ei_raw[i * 2 + 1] != 0u) atomicOr(&bad, 1);
    __syncthreads();
    if (threadIdx.x == 0) g_bad = bad;
}

// ---------------------------------------------------------------------------
// Edge kernel (unchanged — at the L2 LTS cap):
// out[e] = sigmoid(dot(y[src], x_in[dst])), warp = 2 edges, 32B evict-last.
// ---------------------------------------------------------------------------
__global__ void __launch_bounds__(256) edge_bilinear(
    const float* __restrict__ x_in,
    const void* __restrict__ ei,
    float* __restrict__ out,
    int E)
{
    const unsigned int gthread = blockIdx.x * blockDim.x + threadIdx.x;
    const int warp_id = (int)(gthread >> 5);
    const int lane = threadIdx.x & 31;
    const int half = lane >> 4;
    const int sub  = lane & 15;
    const int e    = warp_id * 2 + half;
    if (e >= E) return;

    long long s, d;
    if (g_bad) {
        const int* p = (const int*)ei;
        s = __ldcs(&p[e]);
        d = __ldcs(&p[E + e]);
    } else {
        const long long* p = (const long long*)ei;
        s = __ldcs(&p[e]);
        d = __ldcs(&p[(long long)E + e]);
    }

    float4 a0, a1, b0, b1;
    ldg_el32B(g_y  + s * D + sub * 8, a0, a1);
    ldg_el32B(x_in + d * D + sub * 8, b0, b1);

    float v = a0.x * b0.x + a0.y * b0.y + a0.z * b0.z + a0.w * b0.w
            + a1.x * b1.x + a1.y * b1.y + a1.z * b1.z + a1.w * b1.w;

    #pragma unroll
    for (int o = 8; o > 0; o >>= 1)
        v += __shfl_xor_sync(0xFFFFFFFFu, v, o);

    if (sub == 0)
        __stcs(&out[e], 1.0f / (1.0f + __expf(-v)));
}

// ---------------------------------------------------------------------------
// Launch
// ---------------------------------------------------------------------------
#define GEMM_SMEM ((D * D + 2 * ASZ) * sizeof(float))

extern "C" void kernel_launch(void* const* d_in, const int* in_sizes, int n_in,
                              void* d_out, int out_size)
{
    int i_xin = 0, i_xout = 1, i_ei = 2, i_w = 3;

    if (n_in == 4) {
        int w_idx = -1, ei_idx = -1;
        for (int i = 0; i < 4; i++)
            if (in_sizes[i] == D * D) w_idx = i;
        int idx[3], c = 0;
        for (int i = 0; i < 4; i++) if (i != w_idx) idx[c++] = i;
        if (w_idx >= 0 && c == 3) {
            if (in_sizes[idx[0]] == in_sizes[idx[1]])      { i_xin = idx[0]; i_xout = idx[1]; ei_idx = idx[2]; }
            else if (in_sizes[idx[0]] == in_sizes[idx[2]]) { i_xin = idx[0]; i_xout = idx[2]; ei_idx = idx[1]; }
            else                                            { i_xin = idx[1]; i_xout = idx[2]; ei_idx = idx[0]; }
            i_w = w_idx; i_ei = ei_idx;
        }
    }

    const float* x_in  = (const float*)d_in[i_xin];
    const float* x_out = (const float*)d_in[i_xout];
    const void*  ei    = d_in[i_ei];
    const float* W     = (const float*)d_in[i_w];
    float*       out   = (float*)d_out;

    int n = in_sizes[i_xin] / D;
    if (n > MAX_NODES) n = MAX_NODES;
    int E = in_sizes[i_ei] / 2;

    static int smem_set = 0;
    if (!smem_set) {
        cudaFuncSetAttribute(gemm_xout_w, cudaFuncAttributeMaxDynamicSharedMemorySize,
                             (int)GEMM_SMEM);
        smem_set = 1;
    }

    gemm_xout_w<<<NSM, 1024, GEMM_SMEM>>>(x_out, W, n);

    detect_dtype<<<1, 256>>>((const unsigned int*)ei, in_sizes[i_ei] * 2);

    {
        long long total_threads = ((long long)E + 1) / 2 * 32;
        int blocks = (int)((total_threads + 255) / 256);
        edge_bilinear<<<blocks, 256>>>(x_in, ei, out, E);
    }
}